// round 3
// baseline (speedup 1.0000x reference)
#include <cuda_runtime.h>

// MultiScaleProcessor: images[64,256,256,3] f32 -> out[64,4,256,256,3] f32
// Scales (sorted): 32, 64, 128, 256. Bilinear resize (linspace coords, edge
// clamp), zero-pad centered to 256x256. Scale 256 = passthrough copy.
//
// Structure: one block = 8 output rows of one (batch, scale) image.
//  - p and p+s are multiples of 8 for all scales, so each 8-row block is
//    uniformly zero-band or data-band: no per-row classification.
//  - one row = 768 floats = 192 float4; pad boundaries in floats are
//    multiples of 4 -> every float4 is all-zero or all-data (STG.128 only).
//  - all output stores use .cs streaming hint so the 50MB input stays
//    L2-resident across the 3 resampled scales.

#define ROWS_PER_BLK 8

__global__ void __launch_bounds__(192) msp_kernel(const float* __restrict__ in,
                                                  float* __restrict__ out) {
    const int t  = threadIdx.x;                  // float4 column 0..191
    const int yb = blockIdx.x * ROWS_PER_BLK;    // first row of block
    const int si = blockIdx.y;                   // scale = 32<<si
    const int b  = blockIdx.z;

    const int s = 32 << si;
    const int p = (256 - s) >> 1;

    const float* ib = in + (size_t)b * (256 * 256 * 3);
    float4* obase = reinterpret_cast<float4*>(
        out + (((size_t)b * 4 + si) * 256 + yb) * 768) + t;

    // ---------- native-resolution passthrough: streaming copy ----------
    if (si == 3) {
        const float4* irow = reinterpret_cast<const float4*>(ib + yb * 768) + t;
        float4 v[ROWS_PER_BLK];
#pragma unroll
        for (int r = 0; r < ROWS_PER_BLK; r++) v[r] = __ldg(irow + r * 192);
#pragma unroll
        for (int r = 0; r < ROWS_PER_BLK; r++) __stcs(obase + r * 192, v[r]);
        return;
    }

    const float4 z = make_float4(0.f, 0.f, 0.f, 0.f);
    const int g0 = 4 * t;            // first float index this thread owns
    const int lo = 3 * p;            // data region [lo, hi) in floats
    const int hi = 3 * (p + s);

    // ---------- block fully in the top/bottom padding band, or this
    // ---------- thread in the side padding: pure streaming zero fill ----
    const bool zero_rows = (yb < p) | (yb >= p + s);
    const bool in_band   = (g0 >= lo) & (g0 < hi);
    if (zero_rows || !in_band) {
#pragma unroll
        for (int r = 0; r < ROWS_PER_BLK; r++) __stcs(obase + r * 192, z);
        return;
    }

    // ---------- data band: bilinear ----------
    const float fac = 255.0f / (float)(s - 1);

    // x-interp constants are row-invariant
    int   x0k[4], x1k[4];
    float wxk[4];
#pragma unroll
    for (int k = 0; k < 4; k++) {
        const int rel = g0 + k - lo;
        const int xx  = rel / 3;
        const int c   = rel - 3 * xx;
        const float fx = (float)xx * fac;
        const int x0 = (int)fx;
        wxk[k] = fx - (float)x0;
        x0k[k] = x0 * 3 + c;
        x1k[k] = min(x0 + 1, 255) * 3 + c;
    }

#pragma unroll
    for (int r = 0; r < ROWS_PER_BLK; r++) {
        const int y  = yb + r;
        const int iy = y - p;
        const float fy = (float)iy * fac;
        const int   y0 = (int)fy;
        const float wy = fy - (float)y0;
        const int   y1 = min(y0 + 1, 255);

        const float* __restrict__ r0 = ib + y0 * 768;
        const float* __restrict__ r1 = ib + y1 * 768;

        float res[4];
#pragma unroll
        for (int k = 0; k < 4; k++) {
            const float a  = __ldg(r0 + x0k[k]);
            const float bb = __ldg(r0 + x1k[k]);
            const float cc = __ldg(r1 + x0k[k]);
            const float d  = __ldg(r1 + x1k[k]);
            const float top = a  + (bb - a ) * wxk[k];
            const float bot = cc + (d  - cc) * wxk[k];
            res[k] = top + (bot - top) * wy;
        }
        __stcs(obase + r * 192, make_float4(res[0], res[1], res[2], res[3]));
    }
}

extern "C" void kernel_launch(void* const* d_in, const int* in_sizes, int n_in,
                              void* d_out, int out_size) {
    const float* in = (const float*)d_in[0];
    float* out = (float*)d_out;
    dim3 grid(256 / ROWS_PER_BLK, 4, 64);   // 8192 blocks
    msp_kernel<<<grid, 192>>>(in, out);
}